// round 6
// baseline (speedup 1.0000x reference)
#include <cuda_runtime.h>
#include <cuda_fp16.h>
#include <mma.h>

using namespace nvcuda;

// GPTQ int4 dequant + GEMM: wmma + split-K + cp.async + BK=128 double buffer.
// Inputs fp16-valued f32 (harness upcasts): x:[M,K], scales:[G,N], bias:[N],
// out:[M,N] f32; qweight:[K/8,N] i32, qzeros:[G,N/8] i32, g_idx:[K] i32.

#define THREADS 256
#define BK 128
#define BN 64
#define SPLIT 8
#define MAX_M 64
#define LDA 136  // padded stride in halfs (272B): LDSM banks 4r mod 32, clean

__device__ __half g_xh[MAX_M * 8192];            // 1 MB fp16 x
__device__ float  g_part[SPLIT][MAX_M * 8192];   // partials

__global__ void convert_x_kernel(const float* __restrict__ x, int n) {
    int i = (blockIdx.x * blockDim.x + threadIdx.x) * 4;
    if (i < n) {
        float4 v = *reinterpret_cast<const float4*>(x + i);
        __half2 lo = __floats2half2_rn(v.x, v.y);
        __half2 hi = __floats2half2_rn(v.z, v.w);
        *reinterpret_cast<__half2*>(g_xh + i)     = lo;
        *reinterpret_cast<__half2*>(g_xh + i + 2) = hi;
    }
}

__device__ __forceinline__ unsigned dq_pair(unsigned p, __half2 hz2, __half2 hs2) {
    p |= 0x64006400u;  // two halves: 1024 + nibble (exact)
    __half2 v = __hmul2(__hsub2(*reinterpret_cast<__half2*>(&p), hz2), hs2);
    return *reinterpret_cast<unsigned*>(&v);
}

__device__ __forceinline__ void cp_async16(void* smem_dst, const void* src, bool pred) {
    unsigned s = (unsigned)__cvta_generic_to_shared(smem_dst);
    int sz = pred ? 16 : 0;
    asm volatile("cp.async.cg.shared.global [%0], [%1], 16, %2;\n"
                 :: "r"(s), "l"(src), "r"(sz));
}

__global__ __launch_bounds__(THREADS, 3) void gptq_wmma_kernel(
    const int* __restrict__ qweight, const int* __restrict__ qzeros,
    const float* __restrict__ scales, const int* __restrict__ g_idx,
    int M, int K, int N)
{
    extern __shared__ __align__(16) __half smem[];
    // layout: A0, A1, B0, B1 each 64*LDA halfs
    __half* Abuf[2] = { smem,               smem + 64 * LDA };
    __half* Bbuf[2] = { smem + 2 * 64 * LDA, smem + 3 * 64 * LDA };

    const int tid  = threadIdx.x;
    const int n0   = blockIdx.x * BN;
    const int spl  = blockIdx.y;
    const int Kper = K / SPLIT;          // 1024
    const int kbeg = spl * Kper;
    const int kend = kbeg + Kper;

    // dequant mapping: thread owns column bn; qweight rows kq+4u (u=0..3)
    const int bn   = tid & 63;
    const int kq   = tid >> 6;  // 0..3
    const int gn   = n0 + bn;
    const int zcol = gn >> 3;
    const int zsh  = (gn & 7) * 4;
    const int Nz   = N >> 3;

    // warp tiling: 8 warps -> (4 m16) x (2 n32)
    const int wid = tid >> 5;
    const int mr  = wid & 3;
    const int ng  = wid >> 2;

    // A staging via cp.async: thread covers rows i>>4, 16B seg i&15 (x4)
    const int arow = tid >> 2;          // base pattern for i = tid + u*256
    (void)arow;

    unsigned qReg[4];
    __half2  hz2 = __half2half2(__ushort_as_half(0x6400));
    __half2  hs2 = __half2half2(__ushort_as_half(0));

    auto issue_A = [&](int k0, int buf) {
#pragma unroll
        for (int u = 0; u < 4; ++u) {
            const int i   = tid + u * THREADS;   // 0..1023
            const int row = i >> 4;              // 0..63
            const int seg = i & 15;              // 16B segments (128 halfs/row)
            cp_async16(Abuf[buf] + row * LDA + seg * 8,
                       g_xh + (size_t)row * K + k0 + seg * 8, row < M);
        }
        asm volatile("cp.async.commit_group;\n");
    };

    auto load_q = [&](int k0) {
        const int krow = k0 >> 3;  // 16 qweight rows per chunk
#pragma unroll
        for (int u = 0; u < 4; ++u)
            qReg[u] = (unsigned)qweight[(size_t)(krow + kq + 4 * u) * N + gn];
        const int g = g_idx[k0];   // one group per 128-chunk
        const unsigned zq = (unsigned)qzeros[(size_t)g * Nz + zcol];
        const int z = (int)((zq >> zsh) & 15u) + 1;
        hz2 = __half2half2(__ushort_as_half((unsigned short)(0x6400 + z)));
        hs2 = __half2half2(__float2half_rn(scales[(size_t)g * N + gn]));
    };

    auto stage_B = [&](int buf) {
#pragma unroll
        for (int u = 0; u < 4; ++u) {
            const unsigned q = qReg[u];
            uint4 v;
            v.x = dq_pair((q & 0xFu)         | ((q & 0xF0u) << 12),         hz2, hs2);
            v.y = dq_pair(((q >> 8) & 0xFu)  | (((q >> 8) & 0xF0u) << 12),  hz2, hs2);
            v.z = dq_pair(((q >> 16) & 0xFu) | (((q >> 16) & 0xF0u) << 12), hz2, hs2);
            v.w = dq_pair(((q >> 24) & 0xFu) | (((q >> 24) & 0xF0u) << 12), hz2, hs2);
            *reinterpret_cast<uint4*>(Bbuf[buf] + bn * LDA + (kq + 4 * u) * 8) = v;
        }
    };

    wmma::fragment<wmma::accumulator, 16, 16, 16, float> c[2];
    wmma::fill_fragment(c[0], 0.f);
    wmma::fill_fragment(c[1], 0.f);

    issue_A(kbeg, 0);
    load_q(kbeg);

    int buf = 0;
    for (int k0 = kbeg; k0 < kend; k0 += BK) {
        stage_B(buf);
        asm volatile("cp.async.wait_group 0;\n" ::: "memory");
        __syncthreads();
        if (k0 + BK < kend) {
            issue_A(k0 + BK, buf ^ 1);   // lands in other buffer
            load_q(k0 + BK);             // latency hidden by mma below
        }
#pragma unroll
        for (int ks = 0; ks < BK / 16; ++ks) {
            wmma::fragment<wmma::matrix_a, 16, 16, 16, __half, wmma::row_major> a;
            wmma::load_matrix_sync(a, Abuf[buf] + (mr * 16) * LDA + ks * 16, LDA);
#pragma unroll
            for (int t = 0; t < 2; ++t) {
                wmma::fragment<wmma::matrix_b, 16, 16, 16, __half, wmma::col_major> b;
                wmma::load_matrix_sync(b, Bbuf[buf] + ((ng * 2 + t) * 16) * LDA + ks * 16, LDA);
                wmma::mma_sync(c[t], a, b, c[t]);
            }
        }
        buf ^= 1;
        // single barrier per chunk: writes at iter i+1 target buf^1, whose last
        // readers (mma at i-1) are ordered by the barrier at iter i.
    }

    float* dst = g_part[spl];
#pragma unroll
    for (int t = 0; t < 2; ++t)
        wmma::store_matrix_sync(
            dst + (size_t)(mr * 16) * N + n0 + (ng * 2 + t) * 16,
            c[t], N, wmma::mem_row_major);
}

__global__ __launch_bounds__(THREADS) void reduce_kernel(
    const float* __restrict__ bias, float* __restrict__ out, int M, int N)
{
    const int i4 = (blockIdx.x * blockDim.x + threadIdx.x) * 4;
    if (i4 >= M * N) return;
    float4 s = make_float4(0.f, 0.f, 0.f, 0.f);
#pragma unroll
    for (int p = 0; p < SPLIT; ++p) {
        float4 v = *reinterpret_cast<const float4*>(&g_part[p][i4]);
        s.x += v.x; s.y += v.y; s.z += v.z; s.w += v.w;
    }
    const int n = i4 - (i4 / N) * N;
    float4 b = *reinterpret_cast<const float4*>(bias + n);
    float4 r;
    r.x = __half2float(__float2half_rn(__half2float(__float2half_rn(s.x)) + b.x));
    r.y = __half2float(__float2half_rn(__half2float(__float2half_rn(s.y)) + b.y));
    r.z = __half2float(__float2half_rn(__half2float(__float2half_rn(s.z)) + b.z));
    r.w = __half2float(__float2half_rn(__half2float(__float2half_rn(s.w)) + b.w));
    *reinterpret_cast<float4*>(out + i4) = r;
}

extern "C" void kernel_launch(void* const* d_in, const int* in_sizes, int n_in,
                              void* d_out, int out_size) {
    const float* x       = (const float*)d_in[0];
    const int*   qweight = (const int*)d_in[1];
    const int*   qzeros  = (const int*)d_in[2];
    const float* scales  = (const float*)d_in[3];
    const int*   g_idx   = (const int*)d_in[4];
    const float* bias    = (const float*)d_in[5];
    float*       out     = (float*)d_out;

    const int K = in_sizes[4];      // g_idx length
    const int M = in_sizes[0] / K;  // 64
    const int N = in_sizes[5];      // 8192

    const int smem_bytes = 4 * 64 * LDA * (int)sizeof(__half);  // 69632
    static bool attr_set = false;
    if (!attr_set) {
        cudaFuncSetAttribute(gptq_wmma_kernel,
                             cudaFuncAttributeMaxDynamicSharedMemorySize,
                             smem_bytes);
        attr_set = true;
    }

    const int nx = M * K;
    convert_x_kernel<<<(nx / 4 + THREADS - 1) / THREADS, THREADS>>>(x, nx);

    dim3 grid(N / BN, SPLIT);
    gptq_wmma_kernel<<<grid, THREADS, smem_bytes>>>(qweight, qzeros, scales,
                                                    g_idx, M, K, N);

    const int nout = M * N;
    reduce_kernel<<<(nout / 4 + THREADS - 1) / THREADS, THREADS>>>(bias, out, M, N);
}

// round 8
// speedup vs baseline: 1.0372x; 1.0372x over previous
#include <cuda_runtime.h>
#include <cuda_fp16.h>
#include <mma.h>

using namespace nvcuda;

// GPTQ int4 dequant + GEMM: wmma + split-K, fused x-conversion (round-4
// skeleton, which measured 56.9us; round-5 cp.async/BK=128 variant regressed).
// Inputs fp16-valued f32 (harness upcasts): x:[M,K], scales:[G,N], bias:[N],
// out:[M,N] f32; qweight:[K/8,N] i32, qzeros:[G,N/8] i32, g_idx:[K] i32.
//
// k1: (128 Ntiles x 8 Ksplits) CTAs; M64xN64 tile, K chunk 64, double-buffered
//     SMEM, one barrier per chunk. A staged from f32 x with in-register f16
//     convert (exact: values are fp16-representable). Dequant bit-trick:
//     nib|0x6400 == half(1024+nib); hsub2(1024+z), one hmul2 round == ref W.
// k2: reduce 8 partials, fp16 roundings + bias.

#define THREADS 256
#define BK 64
#define BN 64
#define SPLIT 8
#define MAX_M 64

__device__ float g_part[SPLIT][MAX_M * 8192];  // fp32 partials

__device__ __forceinline__ unsigned dq_pair(unsigned p, __half2 hz2, __half2 hs2) {
    p |= 0x64006400u;  // two halves: 1024 + nibble (exact)
    __half2 v = __hmul2(__hsub2(*reinterpret_cast<__half2*>(&p), hz2), hs2);
    return *reinterpret_cast<unsigned*>(&v);
}

__global__ __launch_bounds__(THREADS, 4) void gptq_wmma_kernel(
    const float* __restrict__ x, const int* __restrict__ qweight,
    const int* __restrict__ qzeros, const float* __restrict__ scales,
    const int* __restrict__ g_idx, int M, int K, int N)
{
    __shared__ __align__(16) __half A[2][64][72];
    __shared__ __align__(16) __half B[2][64][72];

    const int tid  = threadIdx.x;
    const int n0   = blockIdx.x * BN;
    const int spl  = blockIdx.y;
    const int Kper = K / SPLIT;          // 1024
    const int kbeg = spl * Kper;
    const int kend = kbeg + Kper;

    // dequant mapping: thread owns column bn, qweight rows kq and kq+4
    const int bn   = tid & 63;
    const int kq   = tid >> 6;  // 0..3
    const int gn   = n0 + bn;
    const int zcol = gn >> 3;
    const int zsh  = (gn & 7) * 4;
    const int Nz   = N >> 3;

    // warp tiling: 8 warps -> (4 m16) x (2 n32)
    const int wid = tid >> 5;
    const int mr  = wid & 3;
    const int ng  = wid >> 2;

    float4   aF[2][2];     // f32 source for A (converted at stage time)
    unsigned qReg[2];
    __half2  hz2 = __half2half2(__ushort_as_half(0x6400));
    __half2  hs2 = __half2half2(__ushort_as_half(0));

    auto load_chunk = [&](int k0) {
#pragma unroll
        for (int u = 0; u < 2; ++u) {
            const int i = tid + u * THREADS;  // 0..511
            const int row = i >> 3, seg = i & 7;  // seg: 8-half (32B f32) unit
            if (row < M) {
                const float* src = x + (size_t)row * K + k0 + seg * 8;
                aF[u][0] = *reinterpret_cast<const float4*>(src);
                aF[u][1] = *reinterpret_cast<const float4*>(src + 4);
            } else {
                aF[u][0] = make_float4(0.f, 0.f, 0.f, 0.f);
                aF[u][1] = make_float4(0.f, 0.f, 0.f, 0.f);
            }
        }
        const int krow = k0 >> 3;
        qReg[0] = (unsigned)qweight[(size_t)(krow + kq) * N + gn];
        qReg[1] = (unsigned)qweight[(size_t)(krow + kq + 4) * N + gn];
        const int g = g_idx[k0];  // uniform across 64-chunk (groupsize 128)
        const unsigned zq = (unsigned)qzeros[(size_t)g * Nz + zcol];
        const int z = (int)((zq >> zsh) & 15u) + 1;
        hz2 = __half2half2(__ushort_as_half((unsigned short)(0x6400 + z)));
        hs2 = __half2half2(__float2half_rn(scales[(size_t)g * N + gn]));
    };

    auto stage = [&](int buf) {
#pragma unroll
        for (int u = 0; u < 2; ++u) {
            const int i = tid + u * THREADS;
            const int row = i >> 3, seg = i & 7;
            uint4 v;  // 8 halfs from 8 floats (exact round: fp16-valued input)
            __half2 h0 = __floats2half2_rn(aF[u][0].x, aF[u][0].y);
            __half2 h1 = __floats2half2_rn(aF[u][0].z, aF[u][0].w);
            __half2 h2 = __floats2half2_rn(aF[u][1].x, aF[u][1].y);
            __half2 h3 = __floats2half2_rn(aF[u][1].z, aF[u][1].w);
            v.x = *reinterpret_cast<unsigned*>(&h0);
            v.y = *reinterpret_cast<unsigned*>(&h1);
            v.z = *reinterpret_cast<unsigned*>(&h2);
            v.w = *reinterpret_cast<unsigned*>(&h3);
            *reinterpret_cast<uint4*>(&A[buf][row][seg * 8]) = v;
        }
#pragma unroll
        for (int u = 0; u < 2; ++u) {
            const unsigned q = qReg[u];
            uint4 v;
            v.x = dq_pair((q & 0xFu)         | ((q & 0xF0u) << 12),         hz2, hs2);
            v.y = dq_pair(((q >> 8) & 0xFu)  | (((q >> 8) & 0xF0u) << 12),  hz2, hs2);
            v.z = dq_pair(((q >> 16) & 0xFu) | (((q >> 16) & 0xF0u) << 12), hz2, hs2);
            v.w = dq_pair(((q >> 24) & 0xFu) | (((q >> 24) & 0xF0u) << 12), hz2, hs2);
            *reinterpret_cast<uint4*>(&B[buf][bn][(kq + u * 4) * 8]) = v;
        }
    };

    wmma::fragment<wmma::accumulator, 16, 16, 16, float> c[2];
    wmma::fill_fragment(c[0], 0.f);
    wmma::fill_fragment(c[1], 0.f);

    load_chunk(kbeg);
    int buf = 0;
    for (int k0 = kbeg; k0 < kend; k0 += BK) {
        stage(buf);
        __syncthreads();
        if (k0 + BK < kend) load_chunk(k0 + BK);  // overlaps mma below
#pragma unroll
        for (int ks = 0; ks < BK / 16; ++ks) {
            wmma::fragment<wmma::matrix_a, 16, 16, 16, __half, wmma::row_major> a;
            wmma::load_matrix_sync(a, &A[buf][mr * 16][ks * 16], 72);
#pragma unroll
            for (int t = 0; t < 2; ++t) {
                wmma::fragment<wmma::matrix_b, 16, 16, 16, __half, wmma::col_major> b;
                wmma::load_matrix_sync(b, &B[buf][(ng * 2 + t) * 16][ks * 16], 72);
                wmma::mma_sync(c[t], a, b, c[t]);
            }
        }
        buf ^= 1;
        // single barrier per chunk: stage(i+1) writes buf^1, whose last readers
        // (mma at i-1) are ordered by the barrier at iter i.
    }

    float* dst = g_part[spl];
#pragma unroll
    for (int t = 0; t < 2; ++t)
        wmma::store_matrix_sync(
            dst + (size_t)(mr * 16) * N + n0 + (ng * 2 + t) * 16,
            c[t], N, wmma::mem_row_major);
}

__global__ __launch_bounds__(THREADS) void reduce_kernel(
    const float* __restrict__ bias, float* __restrict__ out, int M, int N)
{
    const int i4 = (blockIdx.x * blockDim.x + threadIdx.x) * 4;
    if (i4 >= M * N) return;
    float4 s = make_float4(0.f, 0.f, 0.f, 0.f);
#pragma unroll
    for (int p = 0; p < SPLIT; ++p) {
        float4 v = *reinterpret_cast<const float4*>(&g_part[p][i4]);
        s.x += v.x; s.y += v.y; s.z += v.z; s.w += v.w;
    }
    const int n = i4 - (i4 / N) * N;
    float4 b = *reinterpret_cast<const float4*>(bias + n);
    float4 r;
    r.x = __half2float(__float2half_rn(__half2float(__float2half_rn(s.x)) + b.x));
    r.y = __half2float(__float2half_rn(__half2float(__float2half_rn(s.y)) + b.y));
    r.z = __half2float(__float2half_rn(__half2float(__float2half_rn(s.z)) + b.z));
    r.w = __half2float(__float2half_rn(__half2float(__float2half_rn(s.w)) + b.w));
    *reinterpret_cast<float4*>(out + i4) = r;
}

extern "C" void kernel_launch(void* const* d_in, const int* in_sizes, int n_in,
                              void* d_out, int out_size) {
    const float* x       = (const float*)d_in[0];
    const int*   qweight = (const int*)d_in[1];
    const int*   qzeros  = (const int*)d_in[2];
    const float* scales  = (const float*)d_in[3];
    const int*   g_idx   = (const int*)d_in[4];
    const float* bias    = (const float*)d_in[5];
    float*       out     = (float*)d_out;

    const int K = in_sizes[4];      // g_idx length
    const int M = in_sizes[0] / K;  // 64
    const int N = in_sizes[5];      // 8192

    dim3 grid(N / BN, SPLIT);
    gptq_wmma_kernel<<<grid, THREADS>>>(x, qweight, qzeros, scales, g_idx,
                                        M, K, N);

    const int nout = M * N;
    reduce_kernel<<<(nout / 4 + THREADS - 1) / THREADS, THREADS>>>(bias, out, M, N);
}

// round 10
// speedup vs baseline: 1.1520x; 1.1107x over previous
#include <cuda_runtime.h>
#include <cuda_fp16.h>
#include <mma.h>

using namespace nvcuda;

// GPTQ int4 dequant + GEMM: wmma + split-K (round-4 proven skeleton).
// Inputs fp16-valued f32 (harness upcasts): x:[M,K], scales:[G,N], bias:[N],
// out:[M,N] f32; qweight:[K/8,N] i32, qzeros:[G,N/8] i32, g_idx:[K] i32.
//
// k0: convert x -> fp16 scratch (ILP=4)
// k1: (128 Ntiles x 8 Ksplits) CTAs; M64xN64 tile, K chunk 64, double-buffered
//     SMEM, one barrier per chunk. Dequant bit-trick: nib|0x6400 ==
//     half(1024+nib); hsub2(1024+z), one hmul2 round == ref's fp16 W.
// k2a/k2b: reduce 8 partials (half the M rows each), fp16 roundings + bias.
//          (two reduce launches also align ncu -s 5 -c 1 onto k1)

#define THREADS 256
#define BK 64
#define BN 64
#define SPLIT 8
#define MAX_M 64

__device__ __half g_xh[MAX_M * 8192];            // 1 MB fp16 x
__device__ float  g_part[SPLIT][MAX_M * 8192];   // fp32 partials

__global__ void convert_x_kernel(const float* __restrict__ x, int n) {
    int i = (blockIdx.x * blockDim.x + threadIdx.x) * 16;
    if (i >= n) return;
#pragma unroll
    for (int u = 0; u < 4; ++u) {
        float4 v = *reinterpret_cast<const float4*>(x + i + u * 4);
        __half2 lo = __floats2half2_rn(v.x, v.y);
        __half2 hi = __floats2half2_rn(v.z, v.w);
        *reinterpret_cast<__half2*>(g_xh + i + u * 4)     = lo;
        *reinterpret_cast<__half2*>(g_xh + i + u * 4 + 2) = hi;
    }
}

__device__ __forceinline__ unsigned dq_pair(unsigned p, __half2 hz2, __half2 hs2) {
    p |= 0x64006400u;  // two halves: 1024 + nibble (exact)
    __half2 v = __hmul2(__hsub2(*reinterpret_cast<__half2*>(&p), hz2), hs2);
    return *reinterpret_cast<unsigned*>(&v);
}

__global__ __launch_bounds__(THREADS) void gptq_wmma_kernel(
    const int* __restrict__ qweight, const int* __restrict__ qzeros,
    const float* __restrict__ scales, const int* __restrict__ g_idx,
    int M, int K, int N)
{
    __shared__ __align__(16) __half A[2][64][72];
    __shared__ __align__(16) __half B[2][64][72];

    const int tid  = threadIdx.x;
    const int n0   = blockIdx.x * BN;
    const int spl  = blockIdx.y;
    const int Kper = K / SPLIT;
    const int kbeg = spl * Kper;
    const int kend = kbeg + Kper;

    // dequant mapping: thread owns column bn, qweight rows kq and kq+4
    const int bn   = tid & 63;
    const int kq   = tid >> 6;  // 0..3
    const int gn   = n0 + bn;
    const int zcol = gn >> 3;
    const int zsh  = (gn & 7) * 4;
    const int Nz   = N >> 3;

    // warp tiling: 8 warps -> (4 m16) x (2 n32)
    const int wid = tid >> 5;
    const int mr  = wid & 3;
    const int ng  = wid >> 2;

    uint4    aReg[2];
    unsigned qReg[2];
    __half2  hz2 = __half2half2(__ushort_as_half(0x6400));
    __half2  hs2 = __half2half2(__ushort_as_half(0));

    auto load_chunk = [&](int k0) {
#pragma unroll
        for (int u = 0; u < 2; ++u) {
            const int i = tid + u * THREADS;  // 0..511
            const int row = i >> 3, seg = i & 7;
            if (row < M)
                aReg[u] = *reinterpret_cast<const uint4*>(
                    g_xh + (size_t)row * K + k0 + seg * 8);
            else
                aReg[u] = make_uint4(0u, 0u, 0u, 0u);
        }
        const int krow = k0 >> 3;
        qReg[0] = (unsigned)qweight[(size_t)(krow + kq) * N + gn];
        qReg[1] = (unsigned)qweight[(size_t)(krow + kq + 4) * N + gn];
        const int g = g_idx[k0];  // uniform across 64-chunk (groupsize 128)
        const unsigned zq = (unsigned)qzeros[(size_t)g * Nz + zcol];
        const int z = (int)((zq >> zsh) & 15u) + 1;
        hz2 = __half2half2(__ushort_as_half((unsigned short)(0x6400 + z)));
        hs2 = __half2half2(__float2half_rn(scales[(size_t)g * N + gn]));
    };

    auto stage = [&](int buf) {
#pragma unroll
        for (int u = 0; u < 2; ++u) {
            const int i = tid + u * THREADS;
            const int row = i >> 3, seg = i & 7;
            *reinterpret_cast<uint4*>(&A[buf][row][seg * 8]) = aReg[u];
        }
#pragma unroll
        for (int u = 0; u < 2; ++u) {
            const unsigned q = qReg[u];
            uint4 v;
            v.x = dq_pair((q & 0xFu)         | ((q & 0xF0u) << 12),         hz2, hs2);
            v.y = dq_pair(((q >> 8) & 0xFu)  | (((q >> 8) & 0xF0u) << 12),  hz2, hs2);
            v.z = dq_pair(((q >> 16) & 0xFu) | (((q >> 16) & 0xF0u) << 12), hz2, hs2);
            v.w = dq_pair(((q >> 24) & 0xFu) | (((q >> 24) & 0xF0u) << 12), hz2, hs2);
            *reinterpret_cast<uint4*>(&B[buf][bn][(kq + u * 4) * 8]) = v;
        }
    };

    wmma::fragment<wmma::accumulator, 16, 16, 16, float> c[2];
    wmma::fill_fragment(c[0], 0.f);
    wmma::fill_fragment(c[1], 0.f);

    load_chunk(kbeg);
    int buf = 0;
    for (int k0 = kbeg; k0 < kend; k0 += BK) {
        stage(buf);
        __syncthreads();
        if (k0 + BK < kend) load_chunk(k0 + BK);  // overlaps mma below
#pragma unroll
        for (int ks = 0; ks < BK / 16; ++ks) {
            wmma::fragment<wmma::matrix_a, 16, 16, 16, __half, wmma::row_major> a;
            wmma::load_matrix_sync(a, &A[buf][mr * 16][ks * 16], 72);
#pragma unroll
            for (int t = 0; t < 2; ++t) {
                wmma::fragment<wmma::matrix_b, 16, 16, 16, __half, wmma::col_major> b;
                wmma::load_matrix_sync(b, &B[buf][(ng * 2 + t) * 16][ks * 16], 72);
                wmma::mma_sync(c[t], a, b, c[t]);
            }
        }
        buf ^= 1;
        // single barrier per chunk: stage(i+1) writes buf^1, whose last readers
        // (mma at i-1) are ordered by the barrier at iter i.
    }

    float* dst = g_part[spl];
#pragma unroll
    for (int t = 0; t < 2; ++t)
        wmma::store_matrix_sync(
            dst + (size_t)(mr * 16) * N + n0 + (ng * 2 + t) * 16,
            c[t], N, wmma::mem_row_major);
}

__global__ __launch_bounds__(THREADS) void reduce_kernel(
    const float* __restrict__ bias, float* __restrict__ out,
    int M, int N, int row0)
{
    // handles rows [row0, row0 + M/2)
    const int base = row0 * N;
    const int i4 = base + (blockIdx.x * blockDim.x + threadIdx.x) * 4;
    if (i4 >= base + (M / 2) * N) return;
    float4 s = make_float4(0.f, 0.f, 0.f, 0.f);
#pragma unroll
    for (int p = 0; p < SPLIT; ++p) {
        float4 v = *reinterpret_cast<const float4*>(&g_part[p][i4]);
        s.x += v.x; s.y += v.y; s.z += v.z; s.w += v.w;
    }
    const int n = i4 - (i4 / N) * N;
    float4 b = *reinterpret_cast<const float4*>(bias + n);
    float4 r;
    r.x = __half2float(__float2half_rn(__half2float(__float2half_rn(s.x)) + b.x));
    r.y = __half2float(__float2half_rn(__half2float(__float2half_rn(s.y)) + b.y));
    r.z = __half2float(__float2half_rn(__half2float(__float2half_rn(s.z)) + b.z));
    r.w = __half2float(__float2half_rn(__half2float(__float2half_rn(s.w)) + b.w));
    *reinterpret_cast<float4*>(out + i4) = r;
}

extern "C" void kernel_launch(void* const* d_in, const int* in_sizes, int n_in,
                              void* d_out, int out_size) {
    const float* x       = (const float*)d_in[0];
    const int*   qweight = (const int*)d_in[1];
    const int*   qzeros  = (const int*)d_in[2];
    const float* scales  = (const float*)d_in[3];
    const int*   g_idx   = (const int*)d_in[4];
    const float* bias    = (const float*)d_in[5];
    float*       out     = (float*)d_out;

    const int K = in_sizes[4];      // g_idx length
    const int M = in_sizes[0] / K;  // 64
    const int N = in_sizes[5];      // 8192

    const int nx = M * K;
    convert_x_kernel<<<(nx / 16 + THREADS - 1) / THREADS, THREADS>>>(x, nx);

    dim3 grid(N / BN, SPLIT);
    gptq_wmma_kernel<<<grid, THREADS>>>(qweight, qzeros, scales, g_idx, M, K, N);

    // reduce in two half-M launches (4 launches/call -> ncu -s5 lands on k1)
    const int half = (M / 2) * N;
    reduce_kernel<<<(half / 4 + THREADS - 1) / THREADS, THREADS>>>(
        bias, out, M, N, 0);
    reduce_kernel<<<(half / 4 + THREADS - 1) / THREADS, THREADS>>>(
        bias, out, M, N, M / 2);
}